// round 5
// baseline (speedup 1.0000x reference)
#include <cuda_runtime.h>

#define N_NODES 50000
#define N_EDGES 800000
#define D_IN    256
#define D_HID   128
#define D_OUT   40

#define SCAN_BLK 256
#define N_PART   ((N_NODES + SCAN_BLK - 1) / SCAN_BLK)   // 196

// ---- persistent scratch (no allocations allowed) ----
__device__ int   g_cnt_in [N_NODES];
__device__ int   g_cnt_out[N_NODES];
__device__ int   g_part   [N_PART];
__device__ int   g_pscan  [N_PART];
__device__ int   g_off    [N_NODES + 1];
__device__ int   g_cursor [N_NODES];
__device__ int   g_eidx   [N_EDGES];           // src indices grouped by dst (CSR)
__device__ float g_nsrc   [N_NODES];
__device__ float g_ndst   [N_NODES];
__device__ float g_h0  [(size_t)N_NODES * D_HID];   // (x*nsrc)@W1
__device__ float g_mid [(size_t)N_NODES * D_HID];   // relu(agg*ndst+b1)*nsrc
__device__ float g_h1  [(size_t)N_NODES * D_OUT];   // mid@W2

// ---------------------------------------------------------------------------
__global__ void k_init() {
    int i = blockIdx.x * blockDim.x + threadIdx.x;
    if (i < N_NODES) { g_cnt_in[i] = 0; g_cnt_out[i] = 0; }
}

__global__ void k_hist(const int* __restrict__ src, const int* __restrict__ dst) {
    int i = blockIdx.x * blockDim.x + threadIdx.x;
    if (i < N_EDGES) {
        atomicAdd(&g_cnt_out[src[i]], 1);
        atomicAdd(&g_cnt_in [dst[i]], 1);
    }
}

// phase 1: per-block sums of cnt_in
__global__ __launch_bounds__(SCAN_BLK) void k_part() {
    __shared__ int sh[SCAN_BLK];
    int idx = blockIdx.x * SCAN_BLK + threadIdx.x;
    int v = (idx < N_NODES) ? g_cnt_in[idx] : 0;
    sh[threadIdx.x] = v;
    __syncthreads();
    for (int off = SCAN_BLK / 2; off > 0; off >>= 1) {
        if (threadIdx.x < off) sh[threadIdx.x] += sh[threadIdx.x + off];
        __syncthreads();
    }
    if (threadIdx.x == 0) g_part[blockIdx.x] = sh[0];
}

// phase 2: exclusive scan of the N_PART partials (single small block)
__global__ __launch_bounds__(256) void k_scanpart() {
    __shared__ int sh[256];
    int t = threadIdx.x;
    sh[t] = (t < N_PART) ? g_part[t] : 0;
    __syncthreads();
    for (int off = 1; off < 256; off <<= 1) {
        int v = 0;
        if (t >= off) v = sh[t - off];
        __syncthreads();
        if (t >= off) sh[t] += v;
        __syncthreads();
    }
    if (t < N_PART) g_pscan[t] = (t > 0) ? sh[t - 1] : 0;   // exclusive
    if (t == 0) g_off[N_NODES] = N_EDGES;
}

// phase 3: in-block exclusive scan + block offset -> g_off/g_cursor; fused norms
__global__ __launch_bounds__(SCAN_BLK) void k_apply() {
    __shared__ int sh[SCAN_BLK];
    int t = threadIdx.x;
    int idx = blockIdx.x * SCAN_BLK + t;
    int cin = (idx < N_NODES) ? g_cnt_in[idx] : 0;
    sh[t] = cin;
    __syncthreads();
    for (int off = 1; off < SCAN_BLK; off <<= 1) {
        int v = 0;
        if (t >= off) v = sh[t - off];
        __syncthreads();
        if (t >= off) sh[t] += v;
        __syncthreads();
    }
    if (idx < N_NODES) {
        int excl = sh[t] - cin + g_pscan[blockIdx.x];
        g_off[idx] = excl;
        g_cursor[idx] = excl;
        g_nsrc[idx] = rsqrtf(fmaxf((float)g_cnt_out[idx], 1.0f));
        g_ndst[idx] = rsqrtf(fmaxf((float)cin, 1.0f));
    }
}

__global__ void k_fill(const int* __restrict__ src, const int* __restrict__ dst) {
    int i = blockIdx.x * blockDim.x + threadIdx.x;
    if (i < N_EDGES) {
        int d = dst[i];
        int pos = atomicAdd(&g_cursor[d], 1);
        g_eidx[pos] = src[i];
    }
}

// ---------------------------------------------------------------------------
// GEMM1: g_h0[50000,128] = (x * nsrc[:,None]) @ W1[256,128]
// 128x128x16 tile, 256 threads, 8x8 micro-tile, float4 everywhere.
__global__ __launch_bounds__(256) void k_gemm1(const float* __restrict__ x,
                                               const float* __restrict__ W1) {
    __shared__ float As[16][132];   // transposed A tile [k][row]
    __shared__ float Bs[16][128];   // [k][col]
    const int tid = threadIdx.x;
    const int tx = tid & 15;        // 0..15 -> 8 cols each
    const int ty = tid >> 4;        // 0..15 -> 8 rows each
    const int m0 = blockIdx.x * 128;

    float acc[8][8];
#pragma unroll
    for (int i = 0; i < 8; i++)
#pragma unroll
        for (int j = 0; j < 8; j++) acc[i][j] = 0.0f;

    for (int k0 = 0; k0 < D_IN; k0 += 16) {
        // load A tile (128 rows x 16 k), scaled by nsrc, stored transposed
#pragma unroll
        for (int t = 0; t < 2; t++) {
            int idx = tid + t * 256;      // 0..511
            int r = idx >> 2;             // row 0..127
            int kq = idx & 3;             // float4 within the 16 k's
            int row = m0 + r;
            float4 v = make_float4(0.f, 0.f, 0.f, 0.f);
            float s = 0.0f;
            if (row < N_NODES) {
                v = reinterpret_cast<const float4*>(x + (size_t)row * D_IN + k0)[kq];
                s = g_nsrc[row];
            }
            As[kq * 4 + 0][r] = v.x * s;
            As[kq * 4 + 1][r] = v.y * s;
            As[kq * 4 + 2][r] = v.z * s;
            As[kq * 4 + 3][r] = v.w * s;
        }
        // load B tile (16 k x 128 cols)
#pragma unroll
        for (int t = 0; t < 2; t++) {
            int idx = tid + t * 256;      // 0..511
            int r = idx >> 5;             // k row 0..15
            int c4 = idx & 31;            // float4 col
            float4 w = reinterpret_cast<const float4*>(W1 + (size_t)(k0 + r) * D_HID)[c4];
            reinterpret_cast<float4*>(&Bs[r][c4 * 4])[0] = w;
        }
        __syncthreads();
#pragma unroll
        for (int kk = 0; kk < 16; kk++) {
            float a[8], b[8];
#pragma unroll
            for (int i = 0; i < 8; i++) a[i] = As[kk][ty * 8 + i];
#pragma unroll
            for (int j = 0; j < 8; j++) b[j] = Bs[kk][tx * 8 + j];
#pragma unroll
            for (int i = 0; i < 8; i++)
#pragma unroll
                for (int j = 0; j < 8; j++) acc[i][j] += a[i] * b[j];
        }
        __syncthreads();
    }
#pragma unroll
    for (int i = 0; i < 8; i++) {
        int row = m0 + ty * 8 + i;
        if (row < N_NODES) {
            float4 v0 = make_float4(acc[i][0], acc[i][1], acc[i][2], acc[i][3]);
            float4 v1 = make_float4(acc[i][4], acc[i][5], acc[i][6], acc[i][7]);
            float4* p = reinterpret_cast<float4*>(g_h0 + (size_t)row * D_HID + tx * 8);
            p[0] = v0;
            p[1] = v1;
        }
    }
}

// ---------------------------------------------------------------------------
// gather-aggregate layer 1 (fused with mid transform), warp-per-node, float4:
// mid[n] = relu( (sum_{e: dst=n} h0[src_e]) * ndst[n] + b1 ) * nsrc[n]
__global__ __launch_bounds__(256) void k_gather1(const float* __restrict__ b1) {
    const int warp = threadIdx.x >> 5;
    const int lane = threadIdx.x & 31;
    const int node = blockIdx.x * 8 + warp;
    if (node >= N_NODES) return;
    const int beg = g_off[node], end = g_off[node + 1];
    const float4* __restrict__ h0 = reinterpret_cast<const float4*>(g_h0);

    float4 a0 = make_float4(0.f, 0.f, 0.f, 0.f);
    float4 a1 = make_float4(0.f, 0.f, 0.f, 0.f);
    int i = beg;
    for (; i + 1 < end; i += 2) {
        int s0 = __ldg(&g_eidx[i]);
        int s1 = __ldg(&g_eidx[i + 1]);
        float4 v0 = h0[(size_t)s0 * 32 + lane];
        float4 v1 = h0[(size_t)s1 * 32 + lane];
        a0.x += v0.x; a0.y += v0.y; a0.z += v0.z; a0.w += v0.w;
        a1.x += v1.x; a1.y += v1.y; a1.z += v1.z; a1.w += v1.w;
    }
    if (i < end) {
        int s0 = __ldg(&g_eidx[i]);
        float4 v0 = h0[(size_t)s0 * 32 + lane];
        a0.x += v0.x; a0.y += v0.y; a0.z += v0.z; a0.w += v0.w;
    }
    const float nd = g_ndst[node];
    const float ns = g_nsrc[node];
    const float4 bb = reinterpret_cast<const float4*>(b1)[lane];
    float4 r;
    r.x = fmaxf((a0.x + a1.x) * nd + bb.x, 0.0f) * ns;
    r.y = fmaxf((a0.y + a1.y) * nd + bb.y, 0.0f) * ns;
    r.z = fmaxf((a0.z + a1.z) * nd + bb.z, 0.0f) * ns;
    r.w = fmaxf((a0.w + a1.w) * nd + bb.w, 0.0f) * ns;
    reinterpret_cast<float4*>(g_mid)[(size_t)node * 32 + lane] = r;
}

// ---------------------------------------------------------------------------
// GEMM2: g_h1[50000,40] = g_mid[50000,128] @ W2[128,40]
// 128-row tile, 256 threads, 4x5 micro-tile, k chunked by 16 (transposed smem).
__global__ __launch_bounds__(256) void k_gemm2(const float* __restrict__ W2) {
    __shared__ float w2s[D_HID * D_OUT];   // 20 KB, [k][40]
    __shared__ float hs_t[16][132];        // transposed chunk [k][row], 16B-aligned rows
    const int tid = threadIdx.x;
    const int ry = tid >> 3;               // 0..31 -> 4 rows each
    const int cx = tid & 7;                // 0..7  -> 5 cols each
    const int m0 = blockIdx.x * 128;

    for (int i = tid; i < D_HID * D_OUT; i += 256) w2s[i] = W2[i];

    float acc[4][5];
#pragma unroll
    for (int i = 0; i < 4; i++)
#pragma unroll
        for (int j = 0; j < 5; j++) acc[i][j] = 0.0f;

    for (int k0 = 0; k0 < D_HID; k0 += 16) {
        __syncthreads();
        // load 128 rows x 16 k chunk of g_mid, transposed into hs_t
#pragma unroll
        for (int t = 0; t < 2; t++) {
            int idx = tid + t * 256;       // 0..511
            int r = idx >> 2;              // row 0..127
            int f4 = idx & 3;              // which float4 within 16 k's
            int row = m0 + r;
            float4 v = make_float4(0.f, 0.f, 0.f, 0.f);
            if (row < N_NODES)
                v = reinterpret_cast<const float4*>(g_mid + (size_t)row * D_HID + k0)[f4];
            hs_t[f4 * 4 + 0][r] = v.x;
            hs_t[f4 * 4 + 1][r] = v.y;
            hs_t[f4 * 4 + 2][r] = v.z;
            hs_t[f4 * 4 + 3][r] = v.w;
        }
        __syncthreads();
#pragma unroll
        for (int kk = 0; kk < 16; kk++) {
            float4 a = reinterpret_cast<const float4*>(&hs_t[kk][0])[ry];
            float b[5];
#pragma unroll
            for (int j = 0; j < 5; j++) b[j] = w2s[(k0 + kk) * D_OUT + cx * 5 + j];
#pragma unroll
            for (int j = 0; j < 5; j++) {
                acc[0][j] += a.x * b[j];
                acc[1][j] += a.y * b[j];
                acc[2][j] += a.z * b[j];
                acc[3][j] += a.w * b[j];
            }
        }
    }
#pragma unroll
    for (int i = 0; i < 4; i++) {
        int row = m0 + ry * 4 + i;
        if (row < N_NODES) {
#pragma unroll
            for (int j = 0; j < 5; j++)
                g_h1[(size_t)row * D_OUT + cx * 5 + j] = acc[i][j];
        }
    }
}

// gather-aggregate layer 2 (fused with final bias/norm), 40 threads per node:
// out[n] = (sum_{e: dst=n} h1[src_e]) * ndst[n] + b2
__global__ __launch_bounds__(240) void k_gather2(float* __restrict__ out,
                                                 const float* __restrict__ b2) {
    const int local = threadIdx.x / D_OUT;        // 0..5
    const int c     = threadIdx.x - local * D_OUT; // 0..39
    const int node  = blockIdx.x * 6 + local;
    if (node >= N_NODES) return;
    const int beg = g_off[node], end = g_off[node + 1];
    float acc0 = 0.0f, acc1 = 0.0f;
    int i = beg;
    for (; i + 1 < end; i += 2) {
        int s0 = __ldg(&g_eidx[i]);
        int s1 = __ldg(&g_eidx[i + 1]);
        acc0 += g_h1[(size_t)s0 * D_OUT + c];
        acc1 += g_h1[(size_t)s1 * D_OUT + c];
    }
    if (i < end) acc0 += g_h1[(size_t)__ldg(&g_eidx[i]) * D_OUT + c];
    out[(size_t)node * D_OUT + c] = (acc0 + acc1) * g_ndst[node] + __ldg(&b2[c]);
}

// ---------------------------------------------------------------------------
extern "C" void kernel_launch(void* const* d_in, const int* in_sizes, int n_in,
                              void* d_out, int out_size) {
    const float* x   = (const float*)d_in[0];
    const float* W1  = (const float*)d_in[1];
    const float* b1  = (const float*)d_in[2];
    const float* W2  = (const float*)d_in[3];
    const float* b2  = (const float*)d_in[4];
    const int* esrc  = (const int*)d_in[5];
    const int* edst  = (const int*)d_in[6];
    float* out = (float*)d_out;

    const int T = 256;

    // CSR build + norms (parallel scan)
    k_init<<<(N_NODES + T - 1) / T, T>>>();
    k_hist<<<(N_EDGES + T - 1) / T, T>>>(esrc, edst);
    k_part<<<N_PART, SCAN_BLK>>>();
    k_scanpart<<<1, 256>>>();
    k_apply<<<N_PART, SCAN_BLK>>>();
    k_fill<<<(N_EDGES + T - 1) / T, T>>>(esrc, edst);

    // layer 1
    k_gemm1<<<(N_NODES + 127) / 128, 256>>>(x, W1);
    k_gather1<<<(N_NODES + 7) / 8, 256>>>(b1);

    // layer 2
    k_gemm2<<<(N_NODES + 127) / 128, 256>>>(W2);
    k_gather2<<<(N_NODES + 5) / 6, 240>>>(out, b2);
}

// round 6
// speedup vs baseline: 1.2207x; 1.2207x over previous
#include <cuda_runtime.h>
#include <cstdint>

#define N_NODES 50000
#define N_EDGES 800000
#define D_IN    256
#define D_HID   128
#define D_OUT   40

#define SCAN_BLK 256
#define N_PART   ((N_NODES + SCAN_BLK - 1) / SCAN_BLK)   // 196

// ---- persistent scratch (no allocations allowed) ----
__device__ int   g_cnt_in [N_NODES];
__device__ int   g_cnt_out[N_NODES];
__device__ int   g_part   [N_PART];
__device__ int   g_pscan  [N_PART];
__device__ int   g_off    [N_NODES + 1];
__device__ int   g_cursor [N_NODES];
__device__ int   g_eidx   [N_EDGES];           // src indices grouped by dst (CSR)
__device__ float g_nsrc   [N_NODES];
__device__ float g_ndst   [N_NODES];
__device__ float g_h0  [(size_t)N_NODES * D_HID];   // (x*nsrc)@W1
__device__ float g_mid [(size_t)N_NODES * D_HID];   // relu(agg*ndst+b1)*nsrc
__device__ float g_h1  [(size_t)N_NODES * D_OUT];   // mid@W2

// ---------------------------------------------------------------------------
__global__ void k_init() {
    int i = blockIdx.x * blockDim.x + threadIdx.x;
    if (i < N_NODES) { g_cnt_in[i] = 0; g_cnt_out[i] = 0; }
}

__global__ void k_hist(const int* __restrict__ src, const int* __restrict__ dst) {
    int i = blockIdx.x * blockDim.x + threadIdx.x;
    if (i < N_EDGES) {
        atomicAdd(&g_cnt_out[src[i]], 1);
        atomicAdd(&g_cnt_in [dst[i]], 1);
    }
}

// phase 1: per-block sums of cnt_in
__global__ __launch_bounds__(SCAN_BLK) void k_part() {
    __shared__ int sh[SCAN_BLK];
    int idx = blockIdx.x * SCAN_BLK + threadIdx.x;
    int v = (idx < N_NODES) ? g_cnt_in[idx] : 0;
    sh[threadIdx.x] = v;
    __syncthreads();
    for (int off = SCAN_BLK / 2; off > 0; off >>= 1) {
        if (threadIdx.x < off) sh[threadIdx.x] += sh[threadIdx.x + off];
        __syncthreads();
    }
    if (threadIdx.x == 0) g_part[blockIdx.x] = sh[0];
}

// phase 2: exclusive scan of the N_PART partials (single small block)
__global__ __launch_bounds__(256) void k_scanpart() {
    __shared__ int sh[256];
    int t = threadIdx.x;
    sh[t] = (t < N_PART) ? g_part[t] : 0;
    __syncthreads();
    for (int off = 1; off < 256; off <<= 1) {
        int v = 0;
        if (t >= off) v = sh[t - off];
        __syncthreads();
        if (t >= off) sh[t] += v;
        __syncthreads();
    }
    if (t < N_PART) g_pscan[t] = (t > 0) ? sh[t - 1] : 0;   // exclusive
    if (t == 0) g_off[N_NODES] = N_EDGES;
}

// phase 3: in-block exclusive scan + block offset -> g_off/g_cursor; fused norms
__global__ __launch_bounds__(SCAN_BLK) void k_apply() {
    __shared__ int sh[SCAN_BLK];
    int t = threadIdx.x;
    int idx = blockIdx.x * SCAN_BLK + t;
    int cin = (idx < N_NODES) ? g_cnt_in[idx] : 0;
    sh[t] = cin;
    __syncthreads();
    for (int off = 1; off < SCAN_BLK; off <<= 1) {
        int v = 0;
        if (t >= off) v = sh[t - off];
        __syncthreads();
        if (t >= off) sh[t] += v;
        __syncthreads();
    }
    if (idx < N_NODES) {
        int excl = sh[t] - cin + g_pscan[blockIdx.x];
        g_off[idx] = excl;
        g_cursor[idx] = excl;
        g_nsrc[idx] = rsqrtf(fmaxf((float)g_cnt_out[idx], 1.0f));
        g_ndst[idx] = rsqrtf(fmaxf((float)cin, 1.0f));
    }
}

__global__ void k_fill(const int* __restrict__ src, const int* __restrict__ dst) {
    int i = blockIdx.x * blockDim.x + threadIdx.x;
    if (i < N_EDGES) {
        int d = dst[i];
        int pos = atomicAdd(&g_cursor[d], 1);
        g_eidx[pos] = src[i];
    }
}

// ---------------------------------------------------------------------------
// helpers for tf32 MMA
__device__ __forceinline__ uint32_t f2tf32(float f) {
    uint32_t r;
    asm("cvt.rna.tf32.f32 %0, %1;" : "=r"(r) : "f"(f));
    return r;
}

__device__ __forceinline__ void mma_tf32(float c[4], const uint32_t a[4], const uint32_t b[2]) {
    asm volatile(
        "mma.sync.aligned.m16n8k8.row.col.f32.tf32.tf32.f32 "
        "{%0,%1,%2,%3}, {%4,%5,%6,%7}, {%8,%9}, {%0,%1,%2,%3};"
        : "+f"(c[0]), "+f"(c[1]), "+f"(c[2]), "+f"(c[3])
        : "r"(a[0]), "r"(a[1]), "r"(a[2]), "r"(a[3]), "r"(b[0]), "r"(b[1]));
}

// GEMM1 (TF32 tensor cores): g_h0[50000,128] = (x * nsrc[:,None]) @ W1[256,128]
// block tile 128x128, 8 warps (2x4), warp tile 64x32, k-chunk 32.
// smem layout [k][row]/[k][col] with pad 136 -> fragment loads conflict-free.
__global__ __launch_bounds__(256) void k_gemm1(const float* __restrict__ x,
                                               const float* __restrict__ W1) {
    __shared__ uint32_t As[32][136];   // A^T chunk: [k][row] (tf32 bits, pre-scaled)
    __shared__ uint32_t Bs[32][136];   // B chunk:   [k][col] (tf32 bits)
    const int tid  = threadIdx.x;
    const int wid  = tid >> 5;
    const int lane = tid & 31;
    const int g = lane >> 2;            // 0..7
    const int t = lane & 3;             // 0..3
    const int warp_m = (wid >> 2) * 64; // 0 or 64
    const int warp_n = (wid & 3) * 32;  // 0..96
    const int m0 = blockIdx.x * 128;

    float c[4][4][4];
#pragma unroll
    for (int mt = 0; mt < 4; mt++)
#pragma unroll
        for (int nt = 0; nt < 4; nt++)
#pragma unroll
            for (int j = 0; j < 4; j++) c[mt][nt][j] = 0.0f;

    for (int k0 = 0; k0 < D_IN; k0 += 32) {
        __syncthreads();
        // A chunk: 128 rows x 32 k, scaled by nsrc, tf32, transposed
#pragma unroll
        for (int tt = 0; tt < 4; tt++) {
            int idx = tid + tt * 256;   // 0..1023
            int r  = idx >> 3;          // row 0..127
            int f4 = idx & 7;           // float4 idx within 32 k
            int row = m0 + r;
            float4 v = make_float4(0.f, 0.f, 0.f, 0.f);
            float s = 0.0f;
            if (row < N_NODES) {
                v = reinterpret_cast<const float4*>(x + (size_t)row * D_IN + k0)[f4];
                s = g_nsrc[row];
            }
            As[f4 * 4 + 0][r] = f2tf32(v.x * s);
            As[f4 * 4 + 1][r] = f2tf32(v.y * s);
            As[f4 * 4 + 2][r] = f2tf32(v.z * s);
            As[f4 * 4 + 3][r] = f2tf32(v.w * s);
        }
        // B chunk: 32 k x 128 cols
#pragma unroll
        for (int tt = 0; tt < 4; tt++) {
            int idx = tid + tt * 256;   // 0..1023
            int r  = idx >> 5;          // k row 0..31
            int c4 = idx & 31;          // float4 col
            float4 w = reinterpret_cast<const float4*>(W1 + (size_t)(k0 + r) * D_HID)[c4];
            Bs[r][c4 * 4 + 0] = f2tf32(w.x);
            Bs[r][c4 * 4 + 1] = f2tf32(w.y);
            Bs[r][c4 * 4 + 2] = f2tf32(w.z);
            Bs[r][c4 * 4 + 3] = f2tf32(w.w);
        }
        __syncthreads();
#pragma unroll
        for (int ks = 0; ks < 4; ks++) {
            const int kb = ks * 8;
            uint32_t a[4][4], b[4][2];
#pragma unroll
            for (int mt = 0; mt < 4; mt++) {
                int mr = warp_m + mt * 16;
                a[mt][0] = As[kb + t    ][mr + g];
                a[mt][1] = As[kb + t    ][mr + g + 8];
                a[mt][2] = As[kb + t + 4][mr + g];
                a[mt][3] = As[kb + t + 4][mr + g + 8];
            }
#pragma unroll
            for (int nt = 0; nt < 4; nt++) {
                int nb = warp_n + nt * 8;
                b[nt][0] = Bs[kb + t    ][nb + g];
                b[nt][1] = Bs[kb + t + 4][nb + g];
            }
#pragma unroll
            for (int mt = 0; mt < 4; mt++)
#pragma unroll
                for (int nt = 0; nt < 4; nt++)
                    mma_tf32(c[mt][nt], a[mt], b[nt]);
        }
    }

    // epilogue: c0,c1 -> (row=g, col=2t,2t+1); c2,c3 -> (row=g+8, same cols)
#pragma unroll
    for (int mt = 0; mt < 4; mt++) {
        int row0 = m0 + warp_m + mt * 16 + g;
        int row1 = row0 + 8;
#pragma unroll
        for (int nt = 0; nt < 4; nt++) {
            int col = warp_n + nt * 8 + t * 2;
            if (row0 < N_NODES) {
                float2 v = make_float2(c[mt][nt][0], c[mt][nt][1]);
                *reinterpret_cast<float2*>(g_h0 + (size_t)row0 * D_HID + col) = v;
            }
            if (row1 < N_NODES) {
                float2 v = make_float2(c[mt][nt][2], c[mt][nt][3]);
                *reinterpret_cast<float2*>(g_h0 + (size_t)row1 * D_HID + col) = v;
            }
        }
    }
}

// ---------------------------------------------------------------------------
// gather-aggregate layer 1 (fused with mid transform), warp-per-node, float4:
// mid[n] = relu( (sum_{e: dst=n} h0[src_e]) * ndst[n] + b1 ) * nsrc[n]
__global__ __launch_bounds__(256) void k_gather1(const float* __restrict__ b1) {
    const int warp = threadIdx.x >> 5;
    const int lane = threadIdx.x & 31;
    const int node = blockIdx.x * 8 + warp;
    if (node >= N_NODES) return;
    const int beg = g_off[node], end = g_off[node + 1];
    const float4* __restrict__ h0 = reinterpret_cast<const float4*>(g_h0);

    float4 a0 = make_float4(0.f, 0.f, 0.f, 0.f);
    float4 a1 = make_float4(0.f, 0.f, 0.f, 0.f);
    int i = beg;
    for (; i + 1 < end; i += 2) {
        int s0 = __ldg(&g_eidx[i]);
        int s1 = __ldg(&g_eidx[i + 1]);
        float4 v0 = h0[(size_t)s0 * 32 + lane];
        float4 v1 = h0[(size_t)s1 * 32 + lane];
        a0.x += v0.x; a0.y += v0.y; a0.z += v0.z; a0.w += v0.w;
        a1.x += v1.x; a1.y += v1.y; a1.z += v1.z; a1.w += v1.w;
    }
    if (i < end) {
        int s0 = __ldg(&g_eidx[i]);
        float4 v0 = h0[(size_t)s0 * 32 + lane];
        a0.x += v0.x; a0.y += v0.y; a0.z += v0.z; a0.w += v0.w;
    }
    const float nd = g_ndst[node];
    const float ns = g_nsrc[node];
    const float4 bb = reinterpret_cast<const float4*>(b1)[lane];
    float4 r;
    r.x = fmaxf((a0.x + a1.x) * nd + bb.x, 0.0f) * ns;
    r.y = fmaxf((a0.y + a1.y) * nd + bb.y, 0.0f) * ns;
    r.z = fmaxf((a0.z + a1.z) * nd + bb.z, 0.0f) * ns;
    r.w = fmaxf((a0.w + a1.w) * nd + bb.w, 0.0f) * ns;
    reinterpret_cast<float4*>(g_mid)[(size_t)node * 32 + lane] = r;
}

// ---------------------------------------------------------------------------
// GEMM2: g_h1[50000,40] = g_mid[50000,128] @ W2[128,40]
// 128-row tile, 256 threads, 4x5 micro-tile, k chunked by 16 (transposed smem).
__global__ __launch_bounds__(256) void k_gemm2(const float* __restrict__ W2) {
    __shared__ float w2s[D_HID * D_OUT];   // 20 KB, [k][40]
    __shared__ float hs_t[16][132];        // transposed chunk [k][row]
    const int tid = threadIdx.x;
    const int ry = tid >> 3;               // 0..31 -> 4 rows each
    const int cx = tid & 7;                // 0..7  -> 5 cols each
    const int m0 = blockIdx.x * 128;

    for (int i = tid; i < D_HID * D_OUT; i += 256) w2s[i] = W2[i];

    float acc[4][5];
#pragma unroll
    for (int i = 0; i < 4; i++)
#pragma unroll
        for (int j = 0; j < 5; j++) acc[i][j] = 0.0f;

    for (int k0 = 0; k0 < D_HID; k0 += 16) {
        __syncthreads();
#pragma unroll
        for (int t = 0; t < 2; t++) {
            int idx = tid + t * 256;       // 0..511
            int r = idx >> 2;              // row 0..127
            int f4 = idx & 3;
            int row = m0 + r;
            float4 v = make_float4(0.f, 0.f, 0.f, 0.f);
            if (row < N_NODES)
                v = reinterpret_cast<const float4*>(g_mid + (size_t)row * D_HID + k0)[f4];
            hs_t[f4 * 4 + 0][r] = v.x;
            hs_t[f4 * 4 + 1][r] = v.y;
            hs_t[f4 * 4 + 2][r] = v.z;
            hs_t[f4 * 4 + 3][r] = v.w;
        }
        __syncthreads();
#pragma unroll
        for (int kk = 0; kk < 16; kk++) {
            float4 a = reinterpret_cast<const float4*>(&hs_t[kk][0])[ry];
            float b[5];
#pragma unroll
            for (int j = 0; j < 5; j++) b[j] = w2s[(k0 + kk) * D_OUT + cx * 5 + j];
#pragma unroll
            for (int j = 0; j < 5; j++) {
                acc[0][j] += a.x * b[j];
                acc[1][j] += a.y * b[j];
                acc[2][j] += a.z * b[j];
                acc[3][j] += a.w * b[j];
            }
        }
    }
#pragma unroll
    for (int i = 0; i < 4; i++) {
        int row = m0 + ry * 4 + i;
        if (row < N_NODES) {
#pragma unroll
            for (int j = 0; j < 5; j++)
                g_h1[(size_t)row * D_OUT + cx * 5 + j] = acc[i][j];
        }
    }
}

// gather-aggregate layer 2 (fused with final bias/norm), 40 threads per node:
// out[n] = (sum_{e: dst=n} h1[src_e]) * ndst[n] + b2
__global__ __launch_bounds__(240) void k_gather2(float* __restrict__ out,
                                                 const float* __restrict__ b2) {
    const int local = threadIdx.x / D_OUT;         // 0..5
    const int c     = threadIdx.x - local * D_OUT; // 0..39
    const int node  = blockIdx.x * 6 + local;
    if (node >= N_NODES) return;
    const int beg = g_off[node], end = g_off[node + 1];
    float acc0 = 0.0f, acc1 = 0.0f;
    int i = beg;
    for (; i + 1 < end; i += 2) {
        int s0 = __ldg(&g_eidx[i]);
        int s1 = __ldg(&g_eidx[i + 1]);
        acc0 += g_h1[(size_t)s0 * D_OUT + c];
        acc1 += g_h1[(size_t)s1 * D_OUT + c];
    }
    if (i < end) acc0 += g_h1[(size_t)__ldg(&g_eidx[i]) * D_OUT + c];
    out[(size_t)node * D_OUT + c] = (acc0 + acc1) * g_ndst[node] + __ldg(&b2[c]);
}

// ---------------------------------------------------------------------------
extern "C" void kernel_launch(void* const* d_in, const int* in_sizes, int n_in,
                              void* d_out, int out_size) {
    const float* x   = (const float*)d_in[0];
    const float* W1  = (const float*)d_in[1];
    const float* b1  = (const float*)d_in[2];
    const float* W2  = (const float*)d_in[3];
    const float* b2  = (const float*)d_in[4];
    const int* esrc  = (const int*)d_in[5];
    const int* edst  = (const int*)d_in[6];
    float* out = (float*)d_out;

    const int T = 256;

    // CSR build + norms (parallel scan)
    k_init<<<(N_NODES + T - 1) / T, T>>>();
    k_hist<<<(N_EDGES + T - 1) / T, T>>>(esrc, edst);
    k_part<<<N_PART, SCAN_BLK>>>();
    k_scanpart<<<1, 256>>>();
    k_apply<<<N_PART, SCAN_BLK>>>();
    k_fill<<<(N_EDGES + T - 1) / T, T>>>(esrc, edst);

    // layer 1
    k_gemm1<<<(N_NODES + 127) / 128, 256>>>(x, W1);
    k_gather1<<<(N_NODES + 7) / 8, 256>>>(b1);

    // layer 2
    k_gemm2<<<(N_NODES + 127) / 128, 256>>>(W2);
    k_gather2<<<(N_NODES + 5) / 6, 240>>>(out, b2);
}

// round 7
// speedup vs baseline: 1.4147x; 1.1589x over previous
#include <cuda_runtime.h>
#include <cstdint>

#define N_NODES 50000
#define N_EDGES 800000
#define D_IN    256
#define D_HID   128
#define D_OUT   40

#define SCAN_BLK 256
#define N_PART   ((N_NODES + SCAN_BLK - 1) / SCAN_BLK)   // 196

// ---- persistent scratch (no allocations allowed) ----
__device__ int   g_cnt_in [N_NODES];
__device__ int   g_cnt_out[N_NODES];
__device__ int   g_part   [N_PART];
__device__ int   g_pscan  [N_PART];
__device__ int   g_off    [N_NODES + 1];
__device__ int   g_cursor [N_NODES];
__device__ int   g_eidx   [N_EDGES];           // src indices grouped by dst (CSR)
__device__ float g_nsrc   [N_NODES];
__device__ float g_ndst   [N_NODES];
__device__ float g_h0  [(size_t)N_NODES * D_HID];   // x@W1 (UNSCALED)
__device__ float g_mid [(size_t)N_NODES * D_HID];   // relu(agg*ndst+b1)*nsrc
__device__ float g_h1  [(size_t)N_NODES * D_OUT];   // mid@W2

// ---------------------------------------------------------------------------
__global__ void k_init() {
    int i = blockIdx.x * blockDim.x + threadIdx.x;
    if (i < N_NODES) { g_cnt_in[i] = 0; g_cnt_out[i] = 0; }
}

__global__ void k_hist(const int* __restrict__ src, const int* __restrict__ dst) {
    int i = blockIdx.x * blockDim.x + threadIdx.x;
    if (i < N_EDGES) {
        atomicAdd(&g_cnt_out[src[i]], 1);
        atomicAdd(&g_cnt_in [dst[i]], 1);
    }
}

// phase 1: per-block sums of cnt_in
__global__ __launch_bounds__(SCAN_BLK) void k_part() {
    __shared__ int sh[SCAN_BLK];
    int idx = blockIdx.x * SCAN_BLK + threadIdx.x;
    int v = (idx < N_NODES) ? g_cnt_in[idx] : 0;
    sh[threadIdx.x] = v;
    __syncthreads();
    for (int off = SCAN_BLK / 2; off > 0; off >>= 1) {
        if (threadIdx.x < off) sh[threadIdx.x] += sh[threadIdx.x + off];
        __syncthreads();
    }
    if (threadIdx.x == 0) g_part[blockIdx.x] = sh[0];
}

// phase 2: exclusive scan of the N_PART partials (single small block)
__global__ __launch_bounds__(256) void k_scanpart() {
    __shared__ int sh[256];
    int t = threadIdx.x;
    sh[t] = (t < N_PART) ? g_part[t] : 0;
    __syncthreads();
    for (int off = 1; off < 256; off <<= 1) {
        int v = 0;
        if (t >= off) v = sh[t - off];
        __syncthreads();
        if (t >= off) sh[t] += v;
        __syncthreads();
    }
    if (t < N_PART) g_pscan[t] = (t > 0) ? sh[t - 1] : 0;   // exclusive
    if (t == 0) g_off[N_NODES] = N_EDGES;
}

// phase 3: in-block exclusive scan + block offset -> g_off/g_cursor; fused norms
__global__ __launch_bounds__(SCAN_BLK) void k_apply() {
    __shared__ int sh[SCAN_BLK];
    int t = threadIdx.x;
    int idx = blockIdx.x * SCAN_BLK + t;
    int cin = (idx < N_NODES) ? g_cnt_in[idx] : 0;
    sh[t] = cin;
    __syncthreads();
    for (int off = 1; off < SCAN_BLK; off <<= 1) {
        int v = 0;
        if (t >= off) v = sh[t - off];
        __syncthreads();
        if (t >= off) sh[t] += v;
        __syncthreads();
    }
    if (idx < N_NODES) {
        int excl = sh[t] - cin + g_pscan[blockIdx.x];
        g_off[idx] = excl;
        g_cursor[idx] = excl;
        g_nsrc[idx] = rsqrtf(fmaxf((float)g_cnt_out[idx], 1.0f));
        g_ndst[idx] = rsqrtf(fmaxf((float)cin, 1.0f));
    }
}

__global__ void k_fill(const int* __restrict__ src, const int* __restrict__ dst) {
    int i = blockIdx.x * blockDim.x + threadIdx.x;
    if (i < N_EDGES) {
        int d = dst[i];
        int pos = atomicAdd(&g_cursor[d], 1);
        g_eidx[pos] = src[i];
    }
}

// ---------------------------------------------------------------------------
// helpers for tf32 MMA
__device__ __forceinline__ uint32_t f2tf32(float f) {
    uint32_t r;
    asm("cvt.rna.tf32.f32 %0, %1;" : "=r"(r) : "f"(f));
    return r;
}

__device__ __forceinline__ void mma_tf32(float c[4], const uint32_t a[4], const uint32_t b[2]) {
    asm volatile(
        "mma.sync.aligned.m16n8k8.row.col.f32.tf32.tf32.f32 "
        "{%0,%1,%2,%3}, {%4,%5,%6,%7}, {%8,%9}, {%0,%1,%2,%3};"
        : "+f"(c[0]), "+f"(c[1]), "+f"(c[2]), "+f"(c[3])
        : "r"(a[0]), "r"(a[1]), "r"(a[2]), "r"(a[3]), "r"(b[0]), "r"(b[1]));
}

// GEMM1 (TF32 tensor cores): g_h0[50000,128] = x @ W1[256,128]  (no nsrc scaling;
// scaling moved to gather1 so this kernel has no dependency on the CSR chain).
__global__ __launch_bounds__(256) void k_gemm1(const float* __restrict__ x,
                                               const float* __restrict__ W1) {
    __shared__ uint32_t As[32][136];   // A^T chunk: [k][row] (tf32 bits)
    __shared__ uint32_t Bs[32][136];   // B chunk:   [k][col] (tf32 bits)
    const int tid  = threadIdx.x;
    const int wid  = tid >> 5;
    const int lane = tid & 31;
    const int g = lane >> 2;            // 0..7
    const int t = lane & 3;             // 0..3
    const int warp_m = (wid >> 2) * 64; // 0 or 64
    const int warp_n = (wid & 3) * 32;  // 0..96
    const int m0 = blockIdx.x * 128;

    float c[4][4][4];
#pragma unroll
    for (int mt = 0; mt < 4; mt++)
#pragma unroll
        for (int nt = 0; nt < 4; nt++)
#pragma unroll
            for (int j = 0; j < 4; j++) c[mt][nt][j] = 0.0f;

    for (int k0 = 0; k0 < D_IN; k0 += 32) {
        __syncthreads();
        // A chunk: 128 rows x 32 k, tf32, transposed
#pragma unroll
        for (int tt = 0; tt < 4; tt++) {
            int idx = tid + tt * 256;   // 0..1023
            int r  = idx >> 3;          // row 0..127
            int f4 = idx & 7;           // float4 idx within 32 k
            int row = m0 + r;
            float4 v = make_float4(0.f, 0.f, 0.f, 0.f);
            if (row < N_NODES)
                v = reinterpret_cast<const float4*>(x + (size_t)row * D_IN + k0)[f4];
            As[f4 * 4 + 0][r] = f2tf32(v.x);
            As[f4 * 4 + 1][r] = f2tf32(v.y);
            As[f4 * 4 + 2][r] = f2tf32(v.z);
            As[f4 * 4 + 3][r] = f2tf32(v.w);
        }
        // B chunk: 32 k x 128 cols
#pragma unroll
        for (int tt = 0; tt < 4; tt++) {
            int idx = tid + tt * 256;   // 0..1023
            int r  = idx >> 5;          // k row 0..31
            int c4 = idx & 31;          // float4 col
            float4 w = reinterpret_cast<const float4*>(W1 + (size_t)(k0 + r) * D_HID)[c4];
            Bs[r][c4 * 4 + 0] = f2tf32(w.x);
            Bs[r][c4 * 4 + 1] = f2tf32(w.y);
            Bs[r][c4 * 4 + 2] = f2tf32(w.z);
            Bs[r][c4 * 4 + 3] = f2tf32(w.w);
        }
        __syncthreads();
#pragma unroll
        for (int ks = 0; ks < 4; ks++) {
            const int kb = ks * 8;
            uint32_t a[4][4], b[4][2];
#pragma unroll
            for (int mt = 0; mt < 4; mt++) {
                int mr = warp_m + mt * 16;
                a[mt][0] = As[kb + t    ][mr + g];
                a[mt][1] = As[kb + t    ][mr + g + 8];
                a[mt][2] = As[kb + t + 4][mr + g];
                a[mt][3] = As[kb + t + 4][mr + g + 8];
            }
#pragma unroll
            for (int nt = 0; nt < 4; nt++) {
                int nb = warp_n + nt * 8;
                b[nt][0] = Bs[kb + t    ][nb + g];
                b[nt][1] = Bs[kb + t + 4][nb + g];
            }
#pragma unroll
            for (int mt = 0; mt < 4; mt++)
#pragma unroll
                for (int nt = 0; nt < 4; nt++)
                    mma_tf32(c[mt][nt], a[mt], b[nt]);
        }
    }

    // epilogue
#pragma unroll
    for (int mt = 0; mt < 4; mt++) {
        int row0 = m0 + warp_m + mt * 16 + g;
        int row1 = row0 + 8;
#pragma unroll
        for (int nt = 0; nt < 4; nt++) {
            int col = warp_n + nt * 8 + t * 2;
            if (row0 < N_NODES) {
                float2 v = make_float2(c[mt][nt][0], c[mt][nt][1]);
                *reinterpret_cast<float2*>(g_h0 + (size_t)row0 * D_HID + col) = v;
            }
            if (row1 < N_NODES) {
                float2 v = make_float2(c[mt][nt][2], c[mt][nt][3]);
                *reinterpret_cast<float2*>(g_h0 + (size_t)row1 * D_HID + col) = v;
            }
        }
    }
}

// ---------------------------------------------------------------------------
// gather-aggregate layer 1 (fused with mid transform), warp-per-node, float4.
// h0 is UNSCALED -> apply nsrc[src] per edge here:
// mid[n] = relu( (sum_e h0[src_e]*nsrc[src_e]) * ndst[n] + b1 ) * nsrc[n]
__global__ __launch_bounds__(256) void k_gather1(const float* __restrict__ b1) {
    const int warp = threadIdx.x >> 5;
    const int lane = threadIdx.x & 31;
    const int node = blockIdx.x * 8 + warp;
    if (node >= N_NODES) return;
    const int beg = g_off[node], end = g_off[node + 1];
    const float4* __restrict__ h0 = reinterpret_cast<const float4*>(g_h0);

    float4 a0 = make_float4(0.f, 0.f, 0.f, 0.f);
    float4 a1 = make_float4(0.f, 0.f, 0.f, 0.f);
    int i = beg;
    for (; i + 1 < end; i += 2) {
        int s0 = __ldg(&g_eidx[i]);
        int s1 = __ldg(&g_eidx[i + 1]);
        float n0 = __ldg(&g_nsrc[s0]);
        float n1 = __ldg(&g_nsrc[s1]);
        float4 v0 = h0[(size_t)s0 * 32 + lane];
        float4 v1 = h0[(size_t)s1 * 32 + lane];
        a0.x += v0.x * n0; a0.y += v0.y * n0; a0.z += v0.z * n0; a0.w += v0.w * n0;
        a1.x += v1.x * n1; a1.y += v1.y * n1; a1.z += v1.z * n1; a1.w += v1.w * n1;
    }
    if (i < end) {
        int s0 = __ldg(&g_eidx[i]);
        float n0 = __ldg(&g_nsrc[s0]);
        float4 v0 = h0[(size_t)s0 * 32 + lane];
        a0.x += v0.x * n0; a0.y += v0.y * n0; a0.z += v0.z * n0; a0.w += v0.w * n0;
    }
    const float nd = g_ndst[node];
    const float ns = g_nsrc[node];
    const float4 bb = reinterpret_cast<const float4*>(b1)[lane];
    float4 r;
    r.x = fmaxf((a0.x + a1.x) * nd + bb.x, 0.0f) * ns;
    r.y = fmaxf((a0.y + a1.y) * nd + bb.y, 0.0f) * ns;
    r.z = fmaxf((a0.z + a1.z) * nd + bb.z, 0.0f) * ns;
    r.w = fmaxf((a0.w + a1.w) * nd + bb.w, 0.0f) * ns;
    reinterpret_cast<float4*>(g_mid)[(size_t)node * 32 + lane] = r;
}

// ---------------------------------------------------------------------------
// GEMM2: g_h1[50000,40] = g_mid[50000,128] @ W2[128,40]
__global__ __launch_bounds__(256) void k_gemm2(const float* __restrict__ W2) {
    __shared__ float w2s[D_HID * D_OUT];   // 20 KB, [k][40]
    __shared__ float hs_t[16][132];        // transposed chunk [k][row]
    const int tid = threadIdx.x;
    const int ry = tid >> 3;               // 0..31 -> 4 rows each
    const int cx = tid & 7;                // 0..7  -> 5 cols each
    const int m0 = blockIdx.x * 128;

    for (int i = tid; i < D_HID * D_OUT; i += 256) w2s[i] = W2[i];

    float acc[4][5];
#pragma unroll
    for (int i = 0; i < 4; i++)
#pragma unroll
        for (int j = 0; j < 5; j++) acc[i][j] = 0.0f;

    for (int k0 = 0; k0 < D_HID; k0 += 16) {
        __syncthreads();
#pragma unroll
        for (int t = 0; t < 2; t++) {
            int idx = tid + t * 256;       // 0..511
            int r = idx >> 2;              // row 0..127
            int f4 = idx & 3;
            int row = m0 + r;
            float4 v = make_float4(0.f, 0.f, 0.f, 0.f);
            if (row < N_NODES)
                v = reinterpret_cast<const float4*>(g_mid + (size_t)row * D_HID + k0)[f4];
            hs_t[f4 * 4 + 0][r] = v.x;
            hs_t[f4 * 4 + 1][r] = v.y;
            hs_t[f4 * 4 + 2][r] = v.z;
            hs_t[f4 * 4 + 3][r] = v.w;
        }
        __syncthreads();
#pragma unroll
        for (int kk = 0; kk < 16; kk++) {
            float4 a = reinterpret_cast<const float4*>(&hs_t[kk][0])[ry];
            float b[5];
#pragma unroll
            for (int j = 0; j < 5; j++) b[j] = w2s[(k0 + kk) * D_OUT + cx * 5 + j];
#pragma unroll
            for (int j = 0; j < 5; j++) {
                acc[0][j] += a.x * b[j];
                acc[1][j] += a.y * b[j];
                acc[2][j] += a.z * b[j];
                acc[3][j] += a.w * b[j];
            }
        }
    }
#pragma unroll
    for (int i = 0; i < 4; i++) {
        int row = m0 + ry * 4 + i;
        if (row < N_NODES) {
#pragma unroll
            for (int j = 0; j < 5; j++)
                g_h1[(size_t)row * D_OUT + cx * 5 + j] = acc[i][j];
        }
    }
}

// gather-aggregate layer 2 (fused with final bias/norm), 40 threads per node
__global__ __launch_bounds__(240) void k_gather2(float* __restrict__ out,
                                                 const float* __restrict__ b2) {
    const int local = threadIdx.x / D_OUT;         // 0..5
    const int c     = threadIdx.x - local * D_OUT; // 0..39
    const int node  = blockIdx.x * 6 + local;
    if (node >= N_NODES) return;
    const int beg = g_off[node], end = g_off[node + 1];
    float acc0 = 0.0f, acc1 = 0.0f;
    int i = beg;
    for (; i + 1 < end; i += 2) {
        int s0 = __ldg(&g_eidx[i]);
        int s1 = __ldg(&g_eidx[i + 1]);
        acc0 += g_h1[(size_t)s0 * D_OUT + c];
        acc1 += g_h1[(size_t)s1 * D_OUT + c];
    }
    if (i < end) acc0 += g_h1[(size_t)__ldg(&g_eidx[i]) * D_OUT + c];
    out[(size_t)node * D_OUT + c] = (acc0 + acc1) * g_ndst[node] + __ldg(&b2[c]);
}

// ---------------------------------------------------------------------------
extern "C" void kernel_launch(void* const* d_in, const int* in_sizes, int n_in,
                              void* d_out, int out_size) {
    const float* x   = (const float*)d_in[0];
    const float* W1  = (const float*)d_in[1];
    const float* b1  = (const float*)d_in[2];
    const float* W2  = (const float*)d_in[3];
    const float* b2  = (const float*)d_in[4];
    const int* esrc  = (const int*)d_in[5];
    const int* edst  = (const int*)d_in[6];
    float* out = (float*)d_out;

    const int T = 256;

    // one-time side stream + events (host objects only; reused every call,
    // same launched work each call)
    static cudaStream_t sB = [] { cudaStream_t s; cudaStreamCreateWithFlags(&s, cudaStreamNonBlocking); return s; }();
    static cudaEvent_t evFork = [] { cudaEvent_t e; cudaEventCreateWithFlags(&e, cudaEventDisableTiming); return e; }();
    static cudaEvent_t evJoin = [] { cudaEvent_t e; cudaEventCreateWithFlags(&e, cudaEventDisableTiming); return e; }();

    // fork: CSR build chain on side stream, gemm1 on main stream (independent)
    cudaEventRecord(evFork, 0);
    cudaStreamWaitEvent(sB, evFork, 0);

    k_init<<<(N_NODES + T - 1) / T, T, 0, sB>>>();
    k_hist<<<(N_EDGES + T - 1) / T, T, 0, sB>>>(esrc, edst);
    k_part<<<N_PART, SCAN_BLK, 0, sB>>>();
    k_scanpart<<<1, 256, 0, sB>>>();
    k_apply<<<N_PART, SCAN_BLK, 0, sB>>>();
    k_fill<<<(N_EDGES + T - 1) / T, T, 0, sB>>>(esrc, edst);
    cudaEventRecord(evJoin, sB);

    k_gemm1<<<(N_NODES + 127) / 128, 256>>>(x, W1);

    // join: gather1 needs both h0 and the CSR/norms
    cudaStreamWaitEvent(0, evJoin, 0);
    k_gather1<<<(N_NODES + 7) / 8, 256>>>(b1);

    // layer 2 (serial chain)
    k_gemm2<<<(N_NODES + 127) / 128, 256>>>(W2);
    k_gather2<<<(N_NODES + 5) / 6, 240>>>(out, b2);
}

// round 8
// speedup vs baseline: 1.5231x; 1.0766x over previous
#include <cuda_runtime.h>
#include <cuda_fp16.h>
#include <cstdint>

#define N_NODES 50000
#define N_EDGES 800000
#define D_IN    256
#define D_HID   128
#define D_OUT   40

#define SCAN_BLK 256
#define N_PART   ((N_NODES + SCAN_BLK - 1) / SCAN_BLK)   // 196

// ---- persistent scratch (no allocations allowed) ----
__device__ int    g_cnt_in [N_NODES];
__device__ int    g_cnt_out[N_NODES];
__device__ int    g_part   [N_PART];
__device__ int    g_pscan  [N_PART];
__device__ int    g_off    [N_NODES + 1];
__device__ int    g_cursor [N_NODES];
__device__ int    g_eidx   [N_EDGES];           // src indices grouped by dst (CSR)
__device__ float  g_nsrc   [N_NODES];
__device__ float  g_ndst   [N_NODES];
__device__ __half g_h0h [(size_t)N_NODES * D_HID];  // x@W1 (UNSCALED, fp16)
__device__ float  g_mid [(size_t)N_NODES * D_HID];  // relu(agg*ndst+b1)*nsrc (fp32)
__device__ __half g_h1h [(size_t)N_NODES * D_OUT];  // mid@W2 (fp16)

// ---------------------------------------------------------------------------
__global__ void k_init() {
    int i = blockIdx.x * blockDim.x + threadIdx.x;
    if (i < N_NODES) { g_cnt_in[i] = 0; g_cnt_out[i] = 0; }
}

__global__ void k_hist(const int* __restrict__ src, const int* __restrict__ dst) {
    int i = blockIdx.x * blockDim.x + threadIdx.x;
    if (i < N_EDGES) {
        atomicAdd(&g_cnt_out[src[i]], 1);
        atomicAdd(&g_cnt_in [dst[i]], 1);
    }
}

// phase 1: per-block sums of cnt_in
__global__ __launch_bounds__(SCAN_BLK) void k_part() {
    __shared__ int sh[SCAN_BLK];
    int idx = blockIdx.x * SCAN_BLK + threadIdx.x;
    int v = (idx < N_NODES) ? g_cnt_in[idx] : 0;
    sh[threadIdx.x] = v;
    __syncthreads();
    for (int off = SCAN_BLK / 2; off > 0; off >>= 1) {
        if (threadIdx.x < off) sh[threadIdx.x] += sh[threadIdx.x + off];
        __syncthreads();
    }
    if (threadIdx.x == 0) g_part[blockIdx.x] = sh[0];
}

// phase 2: exclusive scan of the N_PART partials
__global__ __launch_bounds__(256) void k_scanpart() {
    __shared__ int sh[256];
    int t = threadIdx.x;
    sh[t] = (t < N_PART) ? g_part[t] : 0;
    __syncthreads();
    for (int off = 1; off < 256; off <<= 1) {
        int v = 0;
        if (t >= off) v = sh[t - off];
        __syncthreads();
        if (t >= off) sh[t] += v;
        __syncthreads();
    }
    if (t < N_PART) g_pscan[t] = (t > 0) ? sh[t - 1] : 0;   // exclusive
    if (t == 0) g_off[N_NODES] = N_EDGES;
}

// phase 3: in-block exclusive scan + block offset; fused norms
__global__ __launch_bounds__(SCAN_BLK) void k_apply() {
    __shared__ int sh[SCAN_BLK];
    int t = threadIdx.x;
    int idx = blockIdx.x * SCAN_BLK + t;
    int cin = (idx < N_NODES) ? g_cnt_in[idx] : 0;
    sh[t] = cin;
    __syncthreads();
    for (int off = 1; off < SCAN_BLK; off <<= 1) {
        int v = 0;
        if (t >= off) v = sh[t - off];
        __syncthreads();
        if (t >= off) sh[t] += v;
        __syncthreads();
    }
    if (idx < N_NODES) {
        int excl = sh[t] - cin + g_pscan[blockIdx.x];
        g_off[idx] = excl;
        g_cursor[idx] = excl;
        g_nsrc[idx] = rsqrtf(fmaxf((float)g_cnt_out[idx], 1.0f));
        g_ndst[idx] = rsqrtf(fmaxf((float)cin, 1.0f));
    }
}

__global__ void k_fill(const int* __restrict__ src, const int* __restrict__ dst) {
    int i = blockIdx.x * blockDim.x + threadIdx.x;
    if (i < N_EDGES) {
        int d = dst[i];
        int pos = atomicAdd(&g_cursor[d], 1);
        g_eidx[pos] = src[i];
    }
}

// ---------------------------------------------------------------------------
// helpers for tf32 MMA
__device__ __forceinline__ uint32_t f2tf32(float f) {
    uint32_t r;
    asm("cvt.rna.tf32.f32 %0, %1;" : "=r"(r) : "f"(f));
    return r;
}

__device__ __forceinline__ void mma_tf32(float c[4], const uint32_t a[4], const uint32_t b[2]) {
    asm volatile(
        "mma.sync.aligned.m16n8k8.row.col.f32.tf32.tf32.f32 "
        "{%0,%1,%2,%3}, {%4,%5,%6,%7}, {%8,%9}, {%0,%1,%2,%3};"
        : "+f"(c[0]), "+f"(c[1]), "+f"(c[2]), "+f"(c[3])
        : "r"(a[0]), "r"(a[1]), "r"(a[2]), "r"(a[3]), "r"(b[0]), "r"(b[1]));
}

// GEMM1 (TF32): g_h0h[50000,128] = fp16( x @ W1[256,128] )  (unscaled)
__global__ __launch_bounds__(256) void k_gemm1(const float* __restrict__ x,
                                               const float* __restrict__ W1) {
    __shared__ uint32_t As[32][136];   // A^T chunk: [k][row] (tf32 bits)
    __shared__ uint32_t Bs[32][136];   // B chunk:   [k][col] (tf32 bits)
    const int tid  = threadIdx.x;
    const int wid  = tid >> 5;
    const int lane = tid & 31;
    const int g = lane >> 2;            // 0..7
    const int t = lane & 3;             // 0..3
    const int warp_m = (wid >> 2) * 64; // 0 or 64
    const int warp_n = (wid & 3) * 32;  // 0..96
    const int m0 = blockIdx.x * 128;

    float c[4][4][4];
#pragma unroll
    for (int mt = 0; mt < 4; mt++)
#pragma unroll
        for (int nt = 0; nt < 4; nt++)
#pragma unroll
            for (int j = 0; j < 4; j++) c[mt][nt][j] = 0.0f;

    for (int k0 = 0; k0 < D_IN; k0 += 32) {
        __syncthreads();
        // A chunk: 128 rows x 32 k, tf32, transposed
#pragma unroll
        for (int tt = 0; tt < 4; tt++) {
            int idx = tid + tt * 256;   // 0..1023
            int r  = idx >> 3;          // row 0..127
            int f4 = idx & 7;           // float4 idx within 32 k
            int row = m0 + r;
            float4 v = make_float4(0.f, 0.f, 0.f, 0.f);
            if (row < N_NODES)
                v = reinterpret_cast<const float4*>(x + (size_t)row * D_IN + k0)[f4];
            As[f4 * 4 + 0][r] = f2tf32(v.x);
            As[f4 * 4 + 1][r] = f2tf32(v.y);
            As[f4 * 4 + 2][r] = f2tf32(v.z);
            As[f4 * 4 + 3][r] = f2tf32(v.w);
        }
        // B chunk: 32 k x 128 cols
#pragma unroll
        for (int tt = 0; tt < 4; tt++) {
            int idx = tid + tt * 256;   // 0..1023
            int r  = idx >> 5;          // k row 0..31
            int c4 = idx & 31;          // float4 col
            float4 w = reinterpret_cast<const float4*>(W1 + (size_t)(k0 + r) * D_HID)[c4];
            Bs[r][c4 * 4 + 0] = f2tf32(w.x);
            Bs[r][c4 * 4 + 1] = f2tf32(w.y);
            Bs[r][c4 * 4 + 2] = f2tf32(w.z);
            Bs[r][c4 * 4 + 3] = f2tf32(w.w);
        }
        __syncthreads();
#pragma unroll
        for (int ks = 0; ks < 4; ks++) {
            const int kb = ks * 8;
            uint32_t a[4][4], b[4][2];
#pragma unroll
            for (int mt = 0; mt < 4; mt++) {
                int mr = warp_m + mt * 16;
                a[mt][0] = As[kb + t    ][mr + g];
                a[mt][1] = As[kb + t    ][mr + g + 8];
                a[mt][2] = As[kb + t + 4][mr + g];
                a[mt][3] = As[kb + t + 4][mr + g + 8];
            }
#pragma unroll
            for (int nt = 0; nt < 4; nt++) {
                int nb = warp_n + nt * 8;
                b[nt][0] = Bs[kb + t    ][nb + g];
                b[nt][1] = Bs[kb + t + 4][nb + g];
            }
#pragma unroll
            for (int mt = 0; mt < 4; mt++)
#pragma unroll
                for (int nt = 0; nt < 4; nt++)
                    mma_tf32(c[mt][nt], a[mt], b[nt]);
        }
    }

    // epilogue -> fp16
#pragma unroll
    for (int mt = 0; mt < 4; mt++) {
        int row0 = m0 + warp_m + mt * 16 + g;
        int row1 = row0 + 8;
#pragma unroll
        for (int nt = 0; nt < 4; nt++) {
            int col = warp_n + nt * 8 + t * 2;
            if (row0 < N_NODES) {
                __half2 v = __floats2half2_rn(c[mt][nt][0], c[mt][nt][1]);
                *reinterpret_cast<__half2*>(g_h0h + (size_t)row0 * D_HID + col) = v;
            }
            if (row1 < N_NODES) {
                __half2 v = __floats2half2_rn(c[mt][nt][2], c[mt][nt][3]);
                *reinterpret_cast<__half2*>(g_h0h + (size_t)row1 * D_HID + col) = v;
            }
        }
    }
}

// ---------------------------------------------------------------------------
// gather-aggregate layer 1, warp-per-node, fp16 features (8 B / lane / edge):
// mid[n] = relu( (sum_e h0[src_e]*nsrc[src_e]) * ndst[n] + b1 ) * nsrc[n]
__global__ __launch_bounds__(256) void k_gather1(const float* __restrict__ b1) {
    const int warp = threadIdx.x >> 5;
    const int lane = threadIdx.x & 31;
    const int node = blockIdx.x * 8 + warp;
    if (node >= N_NODES) return;
    const int beg = g_off[node], end = g_off[node + 1];

    float4 a0 = make_float4(0.f, 0.f, 0.f, 0.f);
    float4 a1 = make_float4(0.f, 0.f, 0.f, 0.f);
    int i = beg;
    for (; i + 1 < end; i += 2) {
        int s0 = __ldg(&g_eidx[i]);
        int s1 = __ldg(&g_eidx[i + 1]);
        float n0 = __ldg(&g_nsrc[s0]);
        float n1 = __ldg(&g_nsrc[s1]);
        uint2 r0 = *reinterpret_cast<const uint2*>(g_h0h + (size_t)s0 * D_HID + lane * 4);
        uint2 r1 = *reinterpret_cast<const uint2*>(g_h0h + (size_t)s1 * D_HID + lane * 4);
        float2 p00 = __half22float2(*reinterpret_cast<const __half2*>(&r0.x));
        float2 p01 = __half22float2(*reinterpret_cast<const __half2*>(&r0.y));
        float2 p10 = __half22float2(*reinterpret_cast<const __half2*>(&r1.x));
        float2 p11 = __half22float2(*reinterpret_cast<const __half2*>(&r1.y));
        a0.x += p00.x * n0; a0.y += p00.y * n0; a0.z += p01.x * n0; a0.w += p01.y * n0;
        a1.x += p10.x * n1; a1.y += p10.y * n1; a1.z += p11.x * n1; a1.w += p11.y * n1;
    }
    if (i < end) {
        int s0 = __ldg(&g_eidx[i]);
        float n0 = __ldg(&g_nsrc[s0]);
        uint2 r0 = *reinterpret_cast<const uint2*>(g_h0h + (size_t)s0 * D_HID + lane * 4);
        float2 p00 = __half22float2(*reinterpret_cast<const __half2*>(&r0.x));
        float2 p01 = __half22float2(*reinterpret_cast<const __half2*>(&r0.y));
        a0.x += p00.x * n0; a0.y += p00.y * n0; a0.z += p01.x * n0; a0.w += p01.y * n0;
    }
    const float nd = g_ndst[node];
    const float ns = g_nsrc[node];
    const float4 bb = reinterpret_cast<const float4*>(b1)[lane];
    float4 r;
    r.x = fmaxf((a0.x + a1.x) * nd + bb.x, 0.0f) * ns;
    r.y = fmaxf((a0.y + a1.y) * nd + bb.y, 0.0f) * ns;
    r.z = fmaxf((a0.z + a1.z) * nd + bb.z, 0.0f) * ns;
    r.w = fmaxf((a0.w + a1.w) * nd + bb.w, 0.0f) * ns;
    reinterpret_cast<float4*>(g_mid)[(size_t)node * 32 + lane] = r;
}

// ---------------------------------------------------------------------------
// GEMM2: g_h1h[50000,40] = fp16( g_mid[50000,128] @ W2[128,40] )
__global__ __launch_bounds__(256) void k_gemm2(const float* __restrict__ W2) {
    __shared__ float w2s[D_HID * D_OUT];   // 20 KB, [k][40]
    __shared__ float hs_t[16][132];        // transposed chunk [k][row]
    const int tid = threadIdx.x;
    const int ry = tid >> 3;               // 0..31 -> 4 rows each
    const int cx = tid & 7;                // 0..7  -> 5 cols each
    const int m0 = blockIdx.x * 128;

    for (int i = tid; i < D_HID * D_OUT; i += 256) w2s[i] = W2[i];

    float acc[4][5];
#pragma unroll
    for (int i = 0; i < 4; i++)
#pragma unroll
        for (int j = 0; j < 5; j++) acc[i][j] = 0.0f;

    for (int k0 = 0; k0 < D_HID; k0 += 16) {
        __syncthreads();
#pragma unroll
        for (int t = 0; t < 2; t++) {
            int idx = tid + t * 256;       // 0..511
            int r = idx >> 2;              // row 0..127
            int f4 = idx & 3;
            int row = m0 + r;
            float4 v = make_float4(0.f, 0.f, 0.f, 0.f);
            if (row < N_NODES)
                v = reinterpret_cast<const float4*>(g_mid + (size_t)row * D_HID + k0)[f4];
            hs_t[f4 * 4 + 0][r] = v.x;
            hs_t[f4 * 4 + 1][r] = v.y;
            hs_t[f4 * 4 + 2][r] = v.z;
            hs_t[f4 * 4 + 3][r] = v.w;
        }
        __syncthreads();
#pragma unroll
        for (int kk = 0; kk < 16; kk++) {
            float4 a = reinterpret_cast<const float4*>(&hs_t[kk][0])[ry];
            float b[5];
#pragma unroll
            for (int j = 0; j < 5; j++) b[j] = w2s[(k0 + kk) * D_OUT + cx * 5 + j];
#pragma unroll
            for (int j = 0; j < 5; j++) {
                acc[0][j] += a.x * b[j];
                acc[1][j] += a.y * b[j];
                acc[2][j] += a.z * b[j];
                acc[3][j] += a.w * b[j];
            }
        }
    }
#pragma unroll
    for (int i = 0; i < 4; i++) {
        int row = m0 + ry * 4 + i;
        if (row < N_NODES) {
#pragma unroll
            for (int j = 0; j < 5; j++)
                g_h1h[(size_t)row * D_OUT + cx * 5 + j] = __float2half_rn(acc[i][j]);
        }
    }
}

// gather-aggregate layer 2 (fused bias/norm), 20 threads per node (half2 per thread):
// out[n] = (sum_{e: dst=n} h1[src_e]) * ndst[n] + b2
__global__ __launch_bounds__(240) void k_gather2(float* __restrict__ out,
                                                 const float* __restrict__ b2) {
    const int local = threadIdx.x / 20;        // 0..11
    const int c2    = threadIdx.x - local * 20; // 0..19 (channel pair)
    const int node  = blockIdx.x * 12 + local;
    if (node >= N_NODES) return;
    const int beg = g_off[node], end = g_off[node + 1];
    float ax0 = 0.f, ay0 = 0.f, ax1 = 0.f, ay1 = 0.f;
    int i = beg;
    for (; i + 1 < end; i += 2) {
        int s0 = __ldg(&g_eidx[i]);
        int s1 = __ldg(&g_eidx[i + 1]);
        uint r0 = *reinterpret_cast<const uint*>(g_h1h + (size_t)s0 * D_OUT + c2 * 2);
        uint r1 = *reinterpret_cast<const uint*>(g_h1h + (size_t)s1 * D_OUT + c2 * 2);
        float2 p0 = __half22float2(*reinterpret_cast<const __half2*>(&r0));
        float2 p1 = __half22float2(*reinterpret_cast<const __half2*>(&r1));
        ax0 += p0.x; ay0 += p0.y;
        ax1 += p1.x; ay1 += p1.y;
    }
    if (i < end) {
        int s0 = __ldg(&g_eidx[i]);
        uint r0 = *reinterpret_cast<const uint*>(g_h1h + (size_t)s0 * D_OUT + c2 * 2);
        float2 p0 = __half22float2(*reinterpret_cast<const __half2*>(&r0));
        ax0 += p0.x; ay0 += p0.y;
    }
    const float nd = g_ndst[node];
    float2 bb = *reinterpret_cast<const float2*>(b2 + c2 * 2);
    float2 r;
    r.x = (ax0 + ax1) * nd + bb.x;
    r.y = (ay0 + ay1) * nd + bb.y;
    *reinterpret_cast<float2*>(out + (size_t)node * D_OUT + c2 * 2) = r;
}

// ---------------------------------------------------------------------------
extern "C" void kernel_launch(void* const* d_in, const int* in_sizes, int n_in,
                              void* d_out, int out_size) {
    const float* x   = (const float*)d_in[0];
    const float* W1  = (const float*)d_in[1];
    const float* b1  = (const float*)d_in[2];
    const float* W2  = (const float*)d_in[3];
    const float* b2  = (const float*)d_in[4];
    const int* esrc  = (const int*)d_in[5];
    const int* edst  = (const int*)d_in[6];
    float* out = (float*)d_out;

    const int T = 256;

    // one-time side stream + events (host objects only)
    static cudaStream_t sB = [] { cudaStream_t s; cudaStreamCreateWithFlags(&s, cudaStreamNonBlocking); return s; }();
    static cudaEvent_t evFork = [] { cudaEvent_t e; cudaEventCreateWithFlags(&e, cudaEventDisableTiming); return e; }();
    static cudaEvent_t evJoin = [] { cudaEvent_t e; cudaEventCreateWithFlags(&e, cudaEventDisableTiming); return e; }();

    // fork: CSR build chain on side stream, gemm1 on main stream (independent)
    cudaEventRecord(evFork, 0);
    cudaStreamWaitEvent(sB, evFork, 0);

    k_init<<<(N_NODES + T - 1) / T, T, 0, sB>>>();
    k_hist<<<(N_EDGES + T - 1) / T, T, 0, sB>>>(esrc, edst);
    k_part<<<N_PART, SCAN_BLK, 0, sB>>>();
    k_scanpart<<<1, 256, 0, sB>>>();
    k_apply<<<N_PART, SCAN_BLK, 0, sB>>>();
    k_fill<<<(N_EDGES + T - 1) / T, T, 0, sB>>>(esrc, edst);
    cudaEventRecord(evJoin, sB);

    k_gemm1<<<(N_NODES + 127) / 128, 256>>>(x, W1);

    // join: gather1 needs both h0 and the CSR/norms
    cudaStreamWaitEvent(0, evJoin, 0);
    k_gather1<<<(N_NODES + 7) / 8, 256>>>(b1);

    // layer 2 (serial chain)
    k_gemm2<<<(N_NODES + 127) / 128, 256>>>(W2);
    k_gather2<<<(N_NODES + 11) / 12, 240>>>(out, b2);
}

// round 9
// speedup vs baseline: 1.5815x; 1.0384x over previous
#include <cuda_runtime.h>
#include <cuda_fp16.h>
#include <cstdint>

#define N_NODES 50000
#define N_EDGES 800000
#define D_IN    256
#define D_HID   128
#define D_OUT   40

#define SCAN_BLK 256
#define N_PART   ((N_NODES + SCAN_BLK - 1) / SCAN_BLK)   // 196

// ---- persistent scratch (no allocations allowed) ----
__device__ int    g_cnt_in [N_NODES];
__device__ int    g_cnt_out[N_NODES];
__device__ int    g_part   [N_PART];
__device__ int    g_pscan  [N_PART];
__device__ int    g_off    [N_NODES + 1];
__device__ int    g_cursor [N_NODES];
__device__ int    g_eidx   [N_EDGES];           // src indices grouped by dst (CSR)
__device__ float  g_nsrc   [N_NODES];
__device__ float  g_ndst   [N_NODES];
__device__ __half g_h0h [(size_t)N_NODES * D_HID];  // x@W1 (UNSCALED, fp16)
__device__ float  g_mid [(size_t)N_NODES * D_HID];  // relu(agg*ndst+b1)*nsrc (fp32)
__device__ __half g_h1h [(size_t)N_NODES * D_OUT];  // mid@W2 (fp16)

// ---------------------------------------------------------------------------
__global__ void k_init() {
    int i = blockIdx.x * blockDim.x + threadIdx.x;
    if (i < N_NODES) { g_cnt_in[i] = 0; g_cnt_out[i] = 0; }
}

// 4 edges per thread via int4
__global__ void k_hist(const int* __restrict__ src, const int* __restrict__ dst) {
    int i = blockIdx.x * blockDim.x + threadIdx.x;
    if (i < N_EDGES / 4) {
        int4 s = reinterpret_cast<const int4*>(src)[i];
        int4 d = reinterpret_cast<const int4*>(dst)[i];
        atomicAdd(&g_cnt_out[s.x], 1); atomicAdd(&g_cnt_out[s.y], 1);
        atomicAdd(&g_cnt_out[s.z], 1); atomicAdd(&g_cnt_out[s.w], 1);
        atomicAdd(&g_cnt_in [d.x], 1); atomicAdd(&g_cnt_in [d.y], 1);
        atomicAdd(&g_cnt_in [d.z], 1); atomicAdd(&g_cnt_in [d.w], 1);
    }
}

// phase 1: per-block sums of cnt_in
__global__ __launch_bounds__(SCAN_BLK) void k_part() {
    __shared__ int sh[SCAN_BLK];
    int idx = blockIdx.x * SCAN_BLK + threadIdx.x;
    int v = (idx < N_NODES) ? g_cnt_in[idx] : 0;
    sh[threadIdx.x] = v;
    __syncthreads();
    for (int off = SCAN_BLK / 2; off > 0; off >>= 1) {
        if (threadIdx.x < off) sh[threadIdx.x] += sh[threadIdx.x + off];
        __syncthreads();
    }
    if (threadIdx.x == 0) g_part[blockIdx.x] = sh[0];
}

// phase 2: exclusive scan of the N_PART partials
__global__ __launch_bounds__(256) void k_scanpart() {
    __shared__ int sh[256];
    int t = threadIdx.x;
    sh[t] = (t < N_PART) ? g_part[t] : 0;
    __syncthreads();
    for (int off = 1; off < 256; off <<= 1) {
        int v = 0;
        if (t >= off) v = sh[t - off];
        __syncthreads();
        if (t >= off) sh[t] += v;
        __syncthreads();
    }
    if (t < N_PART) g_pscan[t] = (t > 0) ? sh[t - 1] : 0;   // exclusive
    if (t == 0) g_off[N_NODES] = N_EDGES;
}

// phase 3: in-block exclusive scan + block offset; fused norms
__global__ __launch_bounds__(SCAN_BLK) void k_apply() {
    __shared__ int sh[SCAN_BLK];
    int t = threadIdx.x;
    int idx = blockIdx.x * SCAN_BLK + t;
    int cin = (idx < N_NODES) ? g_cnt_in[idx] : 0;
    sh[t] = cin;
    __syncthreads();
    for (int off = 1; off < SCAN_BLK; off <<= 1) {
        int v = 0;
        if (t >= off) v = sh[t - off];
        __syncthreads();
        if (t >= off) sh[t] += v;
        __syncthreads();
    }
    if (idx < N_NODES) {
        int excl = sh[t] - cin + g_pscan[blockIdx.x];
        g_off[idx] = excl;
        g_cursor[idx] = excl;
        g_nsrc[idx] = rsqrtf(fmaxf((float)g_cnt_out[idx], 1.0f));
        g_ndst[idx] = rsqrtf(fmaxf((float)cin, 1.0f));
    }
}

// 4 edges per thread via int4
__global__ void k_fill(const int* __restrict__ src, const int* __restrict__ dst) {
    int i = blockIdx.x * blockDim.x + threadIdx.x;
    if (i < N_EDGES / 4) {
        int4 s = reinterpret_cast<const int4*>(src)[i];
        int4 d = reinterpret_cast<const int4*>(dst)[i];
        g_eidx[atomicAdd(&g_cursor[d.x], 1)] = s.x;
        g_eidx[atomicAdd(&g_cursor[d.y], 1)] = s.y;
        g_eidx[atomicAdd(&g_cursor[d.z], 1)] = s.z;
        g_eidx[atomicAdd(&g_cursor[d.w], 1)] = s.w;
    }
}

// ---------------------------------------------------------------------------
__device__ __forceinline__ void mma_f16(float c[4], const uint32_t a[4], const uint32_t b[2]) {
    asm volatile(
        "mma.sync.aligned.m16n8k16.row.col.f32.f16.f16.f32 "
        "{%0,%1,%2,%3}, {%4,%5,%6,%7}, {%8,%9}, {%0,%1,%2,%3};"
        : "+f"(c[0]), "+f"(c[1]), "+f"(c[2]), "+f"(c[3])
        : "r"(a[0]), "r"(a[1]), "r"(a[2]), "r"(a[3]), "r"(b[0]), "r"(b[1]));
}

// GEMM1 (FP16 MMA, fp32 accum): g_h0h[50000,128] = fp16( x @ W1[256,128] )
// block tile 128x128, 8 warps (2x4), warp tile 64x32, k-chunk 32,
// register double-buffering of global loads. smem half2 [row][kp] pad 20.
#define KP_PAD 20
__global__ __launch_bounds__(256) void k_gemm1(const float* __restrict__ x,
                                               const float* __restrict__ W1) {
    __shared__ __half2 Ah[128][KP_PAD];   // [row][kp]  kp = k/2 (16 used)
    __shared__ __half2 Bh[128][KP_PAD];   // [col][kp]
    const int tid  = threadIdx.x;
    const int wid  = tid >> 5;
    const int lane = tid & 31;
    const int g = lane >> 2;            // 0..7
    const int t = lane & 3;             // 0..3
    const int warp_m = (wid >> 2) * 64; // 0 or 64
    const int warp_n = (wid & 3) * 32;  // 0..96
    const int m0 = blockIdx.x * 128;

    float c[4][4][4];
#pragma unroll
    for (int mt = 0; mt < 4; mt++)
#pragma unroll
        for (int nt = 0; nt < 4; nt++)
#pragma unroll
            for (int j = 0; j < 4; j++) c[mt][nt][j] = 0.0f;

    // prefetch registers: A = 4 float4 (row-chunks), B = 8 (float,float) pairs
    float4 pa[4];
    float2 pb[8];

    // --- load chunk 0 into regs ---
#pragma unroll
    for (int tt = 0; tt < 4; tt++) {
        int linear = tid + tt * 256;       // 0..1023
        int r  = linear >> 3;              // row 0..127
        int f4 = linear & 7;               // float4 within 32 k
        int row = m0 + r;
        pa[tt] = (row < N_NODES)
            ? reinterpret_cast<const float4*>(x + (size_t)row * D_IN)[f4]
            : make_float4(0.f, 0.f, 0.f, 0.f);
    }
#pragma unroll
    for (int tt = 0; tt < 8; tt++) {
        int linear = tid + tt * 256;       // 0..2047
        int kp = linear >> 7;              // 0..15
        int n  = linear & 127;
        pb[tt].x = W1[(size_t)(2 * kp)     * D_HID + n];
        pb[tt].y = W1[(size_t)(2 * kp + 1) * D_HID + n];
    }

    for (int chunk = 0; chunk < D_IN / 32; chunk++) {
        // --- store prefetched regs to smem ---
#pragma unroll
        for (int tt = 0; tt < 4; tt++) {
            int linear = tid + tt * 256;
            int r  = linear >> 3;
            int f4 = linear & 7;
            Ah[r][f4 * 2 + 0] = __floats2half2_rn(pa[tt].x, pa[tt].y);
            Ah[r][f4 * 2 + 1] = __floats2half2_rn(pa[tt].z, pa[tt].w);
        }
#pragma unroll
        for (int tt = 0; tt < 8; tt++) {
            int linear = tid + tt * 256;
            int kp = linear >> 7;
            int n  = linear & 127;
            Bh[n][kp] = __floats2half2_rn(pb[tt].x, pb[tt].y);
        }
        __syncthreads();

        // --- prefetch next chunk (overlaps with MMA below) ---
        if (chunk + 1 < D_IN / 32) {
            int k0n = (chunk + 1) * 32;
#pragma unroll
            for (int tt = 0; tt < 4; tt++) {
                int linear = tid + tt * 256;
                int r  = linear >> 3;
                int f4 = linear & 7;
                int row = m0 + r;
                pa[tt] = (row < N_NODES)
                    ? reinterpret_cast<const float4*>(x + (size_t)row * D_IN + k0n)[f4]
                    : make_float4(0.f, 0.f, 0.f, 0.f);
            }
#pragma unroll
            for (int tt = 0; tt < 8; tt++) {
                int linear = tid + tt * 256;
                int kp = linear >> 7;
                int n  = linear & 127;
                pb[tt].x = W1[(size_t)(k0n + 2 * kp)     * D_HID + n];
                pb[tt].y = W1[(size_t)(k0n + 2 * kp + 1) * D_HID + n];
            }
        }

        // --- MMAs: 2 k-steps of K=16 ---
#pragma unroll
        for (int ks = 0; ks < 2; ks++) {
            const int kb = ks * 8;
            uint32_t a[4][4], b[4][2];
#pragma unroll
            for (int mt = 0; mt < 4; mt++) {
                int mr = warp_m + mt * 16 + g;
                a[mt][0] = *reinterpret_cast<const uint32_t*>(&Ah[mr    ][kb + t    ]);
                a[mt][1] = *reinterpret_cast<const uint32_t*>(&Ah[mr + 8][kb + t    ]);
                a[mt][2] = *reinterpret_cast<const uint32_t*>(&Ah[mr    ][kb + t + 4]);
                a[mt][3] = *reinterpret_cast<const uint32_t*>(&Ah[mr + 8][kb + t + 4]);
            }
#pragma unroll
            for (int nt = 0; nt < 4; nt++) {
                int n = warp_n + nt * 8 + g;
                b[nt][0] = *reinterpret_cast<const uint32_t*>(&Bh[n][kb + t    ]);
                b[nt][1] = *reinterpret_cast<const uint32_t*>(&Bh[n][kb + t + 4]);
            }
#pragma unroll
            for (int mt = 0; mt < 4; mt++)
#pragma unroll
                for (int nt = 0; nt < 4; nt++)
                    mma_f16(c[mt][nt], a[mt], b[nt]);
        }
        __syncthreads();
    }

    // epilogue -> fp16
#pragma unroll
    for (int mt = 0; mt < 4; mt++) {
        int row0 = m0 + warp_m + mt * 16 + g;
        int row1 = row0 + 8;
#pragma unroll
        for (int nt = 0; nt < 4; nt++) {
            int col = warp_n + nt * 8 + t * 2;
            if (row0 < N_NODES) {
                __half2 v = __floats2half2_rn(c[mt][nt][0], c[mt][nt][1]);
                *reinterpret_cast<__half2*>(g_h0h + (size_t)row0 * D_HID + col) = v;
            }
            if (row1 < N_NODES) {
                __half2 v = __floats2half2_rn(c[mt][nt][2], c[mt][nt][3]);
                *reinterpret_cast<__half2*>(g_h0h + (size_t)row1 * D_HID + col) = v;
            }
        }
    }
}

// ---------------------------------------------------------------------------
// gather-aggregate layer 1, warp-per-node, fp16 features, 4-edge unroll:
// mid[n] = relu( (sum_e h0[src_e]*nsrc[src_e]) * ndst[n] + b1 ) * nsrc[n]
__global__ __launch_bounds__(256) void k_gather1(const float* __restrict__ b1) {
    const int warp = threadIdx.x >> 5;
    const int lane = threadIdx.x & 31;
    const int node = blockIdx.x * 8 + warp;
    if (node >= N_NODES) return;
    const int beg = g_off[node], end = g_off[node + 1];

    float4 a0 = make_float4(0.f, 0.f, 0.f, 0.f);
    float4 a1 = make_float4(0.f, 0.f, 0.f, 0.f);
    int i = beg;
    for (; i + 3 < end; i += 4) {
        int s0 = __ldg(&g_eidx[i]);
        int s1 = __ldg(&g_eidx[i + 1]);
        int s2 = __ldg(&g_eidx[i + 2]);
        int s3 = __ldg(&g_eidx[i + 3]);
        float n0 = __ldg(&g_nsrc[s0]);
        float n1 = __ldg(&g_nsrc[s1]);
        float n2 = __ldg(&g_nsrc[s2]);
        float n3 = __ldg(&g_nsrc[s3]);
        uint2 r0 = *reinterpret_cast<const uint2*>(g_h0h + (size_t)s0 * D_HID + lane * 4);
        uint2 r1 = *reinterpret_cast<const uint2*>(g_h0h + (size_t)s1 * D_HID + lane * 4);
        uint2 r2 = *reinterpret_cast<const uint2*>(g_h0h + (size_t)s2 * D_HID + lane * 4);
        uint2 r3 = *reinterpret_cast<const uint2*>(g_h0h + (size_t)s3 * D_HID + lane * 4);
        float2 p0a = __half22float2(*reinterpret_cast<const __half2*>(&r0.x));
        float2 p0b = __half22float2(*reinterpret_cast<const __half2*>(&r0.y));
        float2 p1a = __half22float2(*reinterpret_cast<const __half2*>(&r1.x));
        float2 p1b = __half22float2(*reinterpret_cast<const __half2*>(&r1.y));
        float2 p2a = __half22float2(*reinterpret_cast<const __half2*>(&r2.x));
        float2 p2b = __half22float2(*reinterpret_cast<const __half2*>(&r2.y));
        float2 p3a = __half22float2(*reinterpret_cast<const __half2*>(&r3.x));
        float2 p3b = __half22float2(*reinterpret_cast<const __half2*>(&r3.y));
        a0.x += p0a.x * n0; a0.y += p0a.y * n0; a0.z += p0b.x * n0; a0.w += p0b.y * n0;
        a1.x += p1a.x * n1; a1.y += p1a.y * n1; a1.z += p1b.x * n1; a1.w += p1b.y * n1;
        a0.x += p2a.x * n2; a0.y += p2a.y * n2; a0.z += p2b.x * n2; a0.w += p2b.y * n2;
        a1.x += p3a.x * n3; a1.y += p3a.y * n3; a1.z += p3b.x * n3; a1.w += p3b.y * n3;
    }
    for (; i < end; i++) {
        int s0 = __ldg(&g_eidx[i]);
        float n0 = __ldg(&g_nsrc[s0]);
        uint2 r0 = *reinterpret_cast<const uint2*>(g_h0h + (size_t)s0 * D_HID + lane * 4);
        float2 p0a = __half22float2(*reinterpret_cast<const __half2*>(&r0.x));
        float2 p0b = __half22float2(*reinterpret_cast<const __half2*>(&r0.y));
        a0.x += p0a.x * n0; a0.y += p0a.y * n0; a0.z += p0b.x * n0; a0.w += p0b.y * n0;
    }
    const float nd = g_ndst[node];
    const float ns = g_nsrc[node];
    const float4 bb = reinterpret_cast<const float4*>(b1)[lane];
    float4 r;
    r.x = fmaxf((a0.x + a1.x) * nd + bb.x, 0.0f) * ns;
    r.y = fmaxf((a0.y + a1.y) * nd + bb.y, 0.0f) * ns;
    r.z = fmaxf((a0.z + a1.z) * nd + bb.z, 0.0f) * ns;
    r.w = fmaxf((a0.w + a1.w) * nd + bb.w, 0.0f) * ns;
    reinterpret_cast<float4*>(g_mid)[(size_t)node * 32 + lane] = r;
}

// ---------------------------------------------------------------------------
// GEMM2: g_h1h[50000,40] = fp16( g_mid[50000,128] @ W2[128,40] )
__global__ __launch_bounds__(256) void k_gemm2(const float* __restrict__ W2) {
    __shared__ float w2s[D_HID * D_OUT];   // 20 KB, [k][40]
    __shared__ float hs_t[16][132];        // transposed chunk [k][row]
    const int tid = threadIdx.x;
    const int ry = tid >> 3;               // 0..31 -> 4 rows each
    const int cx = tid & 7;                // 0..7  -> 5 cols each
    const int m0 = blockIdx.x * 128;

    for (int i = tid; i < D_HID * D_OUT; i += 256) w2s[i] = W2[i];

    float acc[4][5];
#pragma unroll
    for (int i = 0; i < 4; i++)
#pragma unroll
        for (int j = 0; j < 5; j++) acc[i][j] = 0.0f;

    for (int k0 = 0; k0 < D_HID; k0 += 16) {
        __syncthreads();
#pragma unroll
        for (int t = 0; t < 2; t++) {
            int idx = tid + t * 256;       // 0..511
            int r = idx >> 2;              // row 0..127
            int f4 = idx & 3;
            int row = m0 + r;
            float4 v = make_float4(0.f, 0.f, 0.f, 0.f);
            if (row < N_NODES)
                v = reinterpret_cast<const float4*>(g_mid + (size_t)row * D_HID + k0)[f4];
            hs_t[f4 * 4 + 0][r] = v.x;
            hs_t[f4 * 4 + 1][r] = v.y;
            hs_t[f4 * 4 + 2][r] = v.z;
            hs_t[f4 * 4 + 3][r] = v.w;
        }
        __syncthreads();
#pragma unroll
        for (int kk = 0; kk < 16; kk++) {
            float4 a = reinterpret_cast<const float4*>(&hs_t[kk][0])[ry];
            float b[5];
#pragma unroll
            for (int j = 0; j < 5; j++) b[j] = w2s[(k0 + kk) * D_OUT + cx * 5 + j];
#pragma unroll
            for (int j = 0; j < 5; j++) {
                acc[0][j] += a.x * b[j];
                acc[1][j] += a.y * b[j];
                acc[2][j] += a.z * b[j];
                acc[3][j] += a.w * b[j];
            }
        }
    }
#pragma unroll
    for (int i = 0; i < 4; i++) {
        int row = m0 + ry * 4 + i;
        if (row < N_NODES) {
#pragma unroll
            for (int j = 0; j < 5; j++)
                g_h1h[(size_t)row * D_OUT + cx * 5 + j] = __float2half_rn(acc[i][j]);
        }
    }
}

// gather-aggregate layer 2 (fused bias/norm), 20 threads per node (half2 per thread)
__global__ __launch_bounds__(240) void k_gather2(float* __restrict__ out,
                                                 const float* __restrict__ b2) {
    const int local = threadIdx.x / 20;        // 0..11
    const int c2    = threadIdx.x - local * 20; // 0..19 (channel pair)
    const int node  = blockIdx.x * 12 + local;
    if (node >= N_NODES) return;
    const int beg = g_off[node], end = g_off[node + 1];
    float ax0 = 0.f, ay0 = 0.f, ax1 = 0.f, ay1 = 0.f;
    int i = beg;
    for (; i + 3 < end; i += 4) {
        int s0 = __ldg(&g_eidx[i]);
        int s1 = __ldg(&g_eidx[i + 1]);
        int s2 = __ldg(&g_eidx[i + 2]);
        int s3 = __ldg(&g_eidx[i + 3]);
        uint r0 = *reinterpret_cast<const uint*>(g_h1h + (size_t)s0 * D_OUT + c2 * 2);
        uint r1 = *reinterpret_cast<const uint*>(g_h1h + (size_t)s1 * D_OUT + c2 * 2);
        uint r2 = *reinterpret_cast<const uint*>(g_h1h + (size_t)s2 * D_OUT + c2 * 2);
        uint r3 = *reinterpret_cast<const uint*>(g_h1h + (size_t)s3 * D_OUT + c2 * 2);
        float2 p0 = __half22float2(*reinterpret_cast<const __half2*>(&r0));
        float2 p1 = __half22float2(*reinterpret_cast<const __half2*>(&r1));
        float2 p2 = __half22float2(*reinterpret_cast<const __half2*>(&r2));
        float2 p3 = __half22float2(*reinterpret_cast<const __half2*>(&r3));
        ax0 += p0.x; ay0 += p0.y;
        ax1 += p1.x; ay1 += p1.y;
        ax0 += p2.x; ay0 += p2.y;
        ax1 += p3.x; ay1 += p3.y;
    }
    for (; i < end; i++) {
        int s0 = __ldg(&g_eidx[i]);
        uint r0 = *reinterpret_cast<const uint*>(g_h1h + (size_t)s0 * D_OUT + c2 * 2);
        float2 p0 = __half22float2(*reinterpret_cast<const __half2*>(&r0));
        ax0 += p0.x; ay0 += p0.y;
    }
    const float nd = g_ndst[node];
    float2 bb = *reinterpret_cast<const float2*>(b2 + c2 * 2);
    float2 r;
    r.x = (ax0 + ax1) * nd + bb.x;
    r.y = (ay0 + ay1) * nd + bb.y;
    *reinterpret_cast<float2*>(out + (size_t)node * D_OUT + c2 * 2) = r;
}

// ---------------------------------------------------------------------------
extern "C" void kernel_launch(void* const* d_in, const int* in_sizes, int n_in,
                              void* d_out, int out_size) {
    const float* x   = (const float*)d_in[0];
    const float* W1  = (const float*)d_in[1];
    const float* b1  = (const float*)d_in[2];
    const float* W2  = (const float*)d_in[3];
    const float* b2  = (const float*)d_in[4];
    const int* esrc  = (const int*)d_in[5];
    const int* edst  = (const int*)d_in[6];
    float* out = (float*)d_out;

    const int T = 256;

    // one-time side stream + events (host objects only)
    static cudaStream_t sB = [] { cudaStream_t s; cudaStreamCreateWithFlags(&s, cudaStreamNonBlocking); return s; }();
    static cudaEvent_t evFork = [] { cudaEvent_t e; cudaEventCreateWithFlags(&e, cudaEventDisableTiming); return e; }();
    static cudaEvent_t evJoin = [] { cudaEvent_t e; cudaEventCreateWithFlags(&e, cudaEventDisableTiming); return e; }();

    // fork: CSR build chain on side stream, gemm1 on main stream (independent)
    cudaEventRecord(evFork, 0);
    cudaStreamWaitEvent(sB, evFork, 0);

    k_init<<<(N_NODES + T - 1) / T, T, 0, sB>>>();
    k_hist<<<(N_EDGES / 4 + T - 1) / T, T, 0, sB>>>(esrc, edst);
    k_part<<<N_PART, SCAN_BLK, 0, sB>>>();
    k_scanpart<<<1, 256, 0, sB>>>();
    k_apply<<<N_PART, SCAN_BLK, 0, sB>>>();
    k_fill<<<(N_EDGES / 4 + T - 1) / T, T, 0, sB>>>(esrc, edst);
    cudaEventRecord(evJoin, sB);

    k_gemm1<<<(N_NODES + 127) / 128, 256>>>(x, W1);

    // join: gather1 needs both h0 and the CSR/norms
    cudaStreamWaitEvent(0, evJoin, 0);
    k_gather1<<<(N_NODES + 7) / 8, 256>>>(b1);

    // layer 2 (serial chain)
    k_gemm2<<<(N_NODES + 127) / 128, 256>>>(W2);
    k_gather2<<<(N_NODES + 11) / 12, 240>>>(out, b2);
}